// round 1
// baseline (speedup 1.0000x reference)
#include <cuda_runtime.h>
#include <cuda_bf16.h>
#include <cstdint>

// Problem constants (from reference): P=8 segments, L=512 codes, D=64, N=1M tokens.
#define PP 8
#define LLEN 512
#define DD 64
#define CC (PP * LLEN)   // 4096 total columns of W

// Scratch for transposed table: Wt[c][d] = W[d][c]. 4096*64*4 = 1 MB.
__device__ float g_Wt[CC * DD];

// ---------------------------------------------------------------------------
// Transpose W [D=64, C=4096] (row-major) -> g_Wt [C=4096, D=64] (row-major).
// Thread t: c = t % 4096 (fastest, so the W read is coalesced),
//           d = t / 4096 (write to g_Wt strided; tiny tensor, cost ~µs).
// ---------------------------------------------------------------------------
__global__ void transpose_w_kernel(const float* __restrict__ W) {
    int t = blockIdx.x * blockDim.x + threadIdx.x;   // 0 .. 4096*64-1
    int c = t & (CC - 1);
    int d = t >> 12;                                 // t / 4096
    if (d < DD) {
        g_Wt[c * DD + d] = W[d * CC + c];
    }
}

// ---------------------------------------------------------------------------
// Gather-and-sum. One warp handles 2 tokens:
//   sub  = lane >> 4  : which of the two tokens
//   q    = lane & 15  : which float4 of the D=64 output
// Each thread: 2 broadcast int4 loads for its token's 8 indices, then
// 8 independent LDG.128 gathers from g_Wt (contiguous 256B per row,
// 16 lanes cover it), accumulate in float4, one coalesced float4 store.
// ---------------------------------------------------------------------------
__global__ void __launch_bounds__(256)
eif_gather_kernel(const int* __restrict__ x, float* __restrict__ out, int n_tok) {
    int warp_id = (blockIdx.x * blockDim.x + threadIdx.x) >> 5;
    int lane    = threadIdx.x & 31;
    int tok0    = warp_id << 1;                 // first token of this warp's pair
    int sub     = lane >> 4;                    // 0 or 1
    int q       = lane & 15;                    // float4 slot within D
    int tok     = tok0 + sub;
    if (tok >= n_tok) return;

    // 8 int32 codes for this token, as two 16B broadcast loads.
    const int4* xv = reinterpret_cast<const int4*>(x);
    int4 i0 = xv[tok * 2 + 0];                  // codes 0..3
    int4 i1 = xv[tok * 2 + 1];                  // codes 4..7

    const float4* __restrict__ Wt4 = reinterpret_cast<const float4*>(g_Wt);

    float4 acc = make_float4(0.f, 0.f, 0.f, 0.f);
    int rows[8];
    rows[0] = 0 * LLEN + i0.x;
    rows[1] = 1 * LLEN + i0.y;
    rows[2] = 2 * LLEN + i0.z;
    rows[3] = 3 * LLEN + i0.w;
    rows[4] = 4 * LLEN + i1.x;
    rows[5] = 5 * LLEN + i1.y;
    rows[6] = 6 * LLEN + i1.z;
    rows[7] = 7 * LLEN + i1.w;

#pragma unroll
    for (int p = 0; p < 8; p++) {
        // Row is 64 floats = 16 float4; this thread takes slot q.
        float4 v = __ldg(&Wt4[rows[p] * 16 + q]);
        acc.x += v.x; acc.y += v.y; acc.z += v.z; acc.w += v.w;
    }

    reinterpret_cast<float4*>(out)[tok * 16 + q] = acc;
}

// ---------------------------------------------------------------------------
// kernel_launch: d_in[0] = x (int32, N*8), d_in[1] = W (float32, 64*4096).
// d_out = float32, N*64.
// ---------------------------------------------------------------------------
extern "C" void kernel_launch(void* const* d_in, const int* in_sizes, int n_in,
                              void* d_out, int out_size) {
    const int*   x = (const int*)d_in[0];
    const float* W = (const float*)d_in[1];
    float*       out = (float*)d_out;

    int n_tok = in_sizes[0] / PP;   // N

    // 1) Transpose W into the device scratch.
    {
        int total = CC * DD;        // 262144
        int threads = 256;
        int blocks = (total + threads - 1) / threads;
        transpose_w_kernel<<<blocks, threads>>>(W);
    }

    // 2) Gather-and-sum. 2 tokens per warp, 8 warps per block -> 16 tokens/block.
    {
        int threads = 256;
        long long warps_needed = ((long long)n_tok + 1) / 2;
        long long blocks = (warps_needed + 7) / 8;
        eif_gather_kernel<<<(unsigned)blocks, threads>>>(x, out, n_tok);
    }
}

// round 2
// speedup vs baseline: 1.1508x; 1.1508x over previous
#include <cuda_runtime.h>
#include <cuda_fp16.h>
#include <cstdint>

// Problem constants: P=8 segments, L=512 codes, D=64, N=1M tokens.
#define PP 8
#define LLEN 512
#define DD 64
#define CC (PP * LLEN)   // 4096 rows in transposed table

// Transposed + fp16-converted table: g_Wh[c][d] = (half)W[d][c].
// 4096 * 64 * 2B = 512 KB -> fully L2-resident, rows are 128B contiguous.
__device__ __half g_Wh[CC * DD];

// ---------------------------------------------------------------------------
// Transpose+convert W [D=64, C=4096] fp32 row-major -> g_Wh [C=4096, D=64] fp16.
// c fastest so the W read is coalesced. Tiny (~µs).
// ---------------------------------------------------------------------------
__global__ void convert_w_kernel(const float* __restrict__ W) {
    int t = blockIdx.x * blockDim.x + threadIdx.x;   // 0 .. 262143
    int c = t & (CC - 1);
    int d = t >> 12;
    if (d < DD) {
        g_Wh[c * DD + d] = __float2half(W[d * CC + c]);
    }
}

// ---------------------------------------------------------------------------
// Gather-and-sum, fp16 table, fp32 accumulate.
// One warp = 4 tokens: tok = warp*4 + (lane>>3), s = lane&7.
// Row = 64 halfs = 128B = 8 lanes x LDG.128. Each lane owns 8 consecutive
// output floats [8s, 8s+8).
// ---------------------------------------------------------------------------
__global__ void __launch_bounds__(256)
eif_gather_h_kernel(const int* __restrict__ x, float* __restrict__ out, int n_tok) {
    int warp_id = (blockIdx.x * blockDim.x + threadIdx.x) >> 5;
    int lane    = threadIdx.x & 31;
    int tok     = (warp_id << 2) + (lane >> 3);
    int s       = lane & 7;                      // 16B slot within the 128B row
    if (tok >= n_tok) return;

    // 8 int32 codes for this token (two 16B loads, broadcast across 8 lanes).
    const int4* xv = reinterpret_cast<const int4*>(x);
    int4 i0 = xv[tok * 2 + 0];
    int4 i1 = xv[tok * 2 + 1];

    int rows[8];
    rows[0] = 0 * LLEN + i0.x;
    rows[1] = 1 * LLEN + i0.y;
    rows[2] = 2 * LLEN + i0.z;
    rows[3] = 3 * LLEN + i0.w;
    rows[4] = 4 * LLEN + i1.x;
    rows[5] = 5 * LLEN + i1.y;
    rows[6] = 6 * LLEN + i1.z;
    rows[7] = 7 * LLEN + i1.w;

    const uint4* __restrict__ Wh4 = reinterpret_cast<const uint4*>(g_Wh);
    // Row stride in uint4 units: 128B / 16B = 8.

    float2 a0 = make_float2(0.f, 0.f);
    float2 a1 = make_float2(0.f, 0.f);
    float2 a2 = make_float2(0.f, 0.f);
    float2 a3 = make_float2(0.f, 0.f);

#pragma unroll
    for (int p = 0; p < 8; p++) {
        uint4 v = Wh4[rows[p] * 8 + s];          // 8 halfs
        float2 f0 = __half22float2(*reinterpret_cast<__half2*>(&v.x));
        float2 f1 = __half22float2(*reinterpret_cast<__half2*>(&v.y));
        float2 f2 = __half22float2(*reinterpret_cast<__half2*>(&v.z));
        float2 f3 = __half22float2(*reinterpret_cast<__half2*>(&v.w));
        a0.x += f0.x; a0.y += f0.y;
        a1.x += f1.x; a1.y += f1.y;
        a2.x += f2.x; a2.y += f2.y;
        a3.x += f3.x; a3.y += f3.y;
    }

    // Lane s writes floats [8s, 8s+8) of this token's 64-float output row.
    float4* o = reinterpret_cast<float4*>(out + (size_t)tok * DD + s * 8);
    o[0] = make_float4(a0.x, a0.y, a1.x, a1.y);
    o[1] = make_float4(a2.x, a2.y, a3.x, a3.y);
}

// ---------------------------------------------------------------------------
// kernel_launch: d_in[0] = x (int32, N*8), d_in[1] = W (float32, 64*4096).
// d_out = float32, N*64.
// ---------------------------------------------------------------------------
extern "C" void kernel_launch(void* const* d_in, const int* in_sizes, int n_in,
                              void* d_out, int out_size) {
    const int*   x = (const int*)d_in[0];
    const float* W = (const float*)d_in[1];
    float*       out = (float*)d_out;

    int n_tok = in_sizes[0] / PP;   // N

    // 1) Convert + transpose table to fp16.
    {
        int total = CC * DD;        // 262144
        convert_w_kernel<<<total / 256, 256>>>(W);
    }

    // 2) Gather-and-sum: 4 tokens/warp, 8 warps/block -> 32 tokens/block.
    {
        int threads = 256;
        long long warps_needed = ((long long)n_tok + 3) / 4;
        long long blocks = (warps_needed + 7) / 8;
        eif_gather_h_kernel<<<(unsigned)blocks, threads>>>(x, out, n_tok);
    }
}